// round 1
// baseline (speedup 1.0000x reference)
#include <cuda_runtime.h>

#define N_NODES  100000
#define N_EDGES  3200000
#define N_GRAPHS 512
#define F1 35
#define F2 128
#define KDIM 70   // concat of [agg | self] features

// ---------------- device scratch (no allocations allowed) ----------------
__device__ int   d_cnt[N_NODES];
__device__ int   d_off[N_NODES + 1];
__device__ int   d_cur[N_NODES];
__device__ int   d_csr_src[N_EDGES];
__device__ float d_agg[N_NODES * F1];
__device__ float d_h1[N_NODES * F1];
__device__ int   d_gmax[N_GRAPHS * F2];

// monotonic float->int key (involution), preserves ordering under int compare
__device__ __forceinline__ int fkey(float f) {
    int i = __float_as_int(f);
    return i >= 0 ? i : (i ^ 0x7FFFFFFF);
}

// ---------------- init: zero degree counts, set pool identity ----------------
__global__ void init_kernel() {
    int i = blockIdx.x * blockDim.x + threadIdx.x;
    if (i < N_NODES) d_cnt[i] = 0;
    if (i < N_GRAPHS * F2) d_gmax[i] = (int)0x807FFFFFu;  // fkey(-inf)
}

// ---------------- degree count ----------------
__global__ void count_kernel(const int* __restrict__ dst) {
    int e = blockIdx.x * blockDim.x + threadIdx.x;
    if (e < N_EDGES) atomicAdd(&d_cnt[dst[e]], 1);
}

// ---------------- single-block exclusive scan (4 elems/thread/iter) ----------------
__global__ void scan_kernel() {
    __shared__ int wsum[33];
    __shared__ int s_carry;
    const int tid = threadIdx.x;
    const int lane = tid & 31;
    const int wid = tid >> 5;
    if (tid == 0) s_carry = 0;
    __syncthreads();
    for (int base = 0; base < N_NODES; base += 4096) {
        int i0 = base + tid * 4;
        int v0 = (i0 + 0 < N_NODES) ? d_cnt[i0 + 0] : 0;
        int v1 = (i0 + 1 < N_NODES) ? d_cnt[i0 + 1] : 0;
        int v2 = (i0 + 2 < N_NODES) ? d_cnt[i0 + 2] : 0;
        int v3 = (i0 + 3 < N_NODES) ? d_cnt[i0 + 3] : 0;
        int tsum = v0 + v1 + v2 + v3;
        int incl = tsum;
#pragma unroll
        for (int s = 1; s < 32; s <<= 1) {
            int t = __shfl_up_sync(0xffffffffu, incl, s);
            if (lane >= s) incl += t;
        }
        if (lane == 31) wsum[wid] = incl;
        __syncthreads();
        int carry = s_carry;
        if (wid == 0) {
            int w = wsum[lane];
            int wi = w;
#pragma unroll
            for (int s = 1; s < 32; s <<= 1) {
                int t = __shfl_up_sync(0xffffffffu, wi, s);
                if (lane >= s) wi += t;
            }
            wsum[lane] = wi - w;
            if (lane == 31) wsum[32] = wi;
        }
        __syncthreads();
        int run = carry + wsum[wid] + (incl - tsum);
        if (i0 + 0 < N_NODES) { d_off[i0 + 0] = run; d_cur[i0 + 0] = run; } run += v0;
        if (i0 + 1 < N_NODES) { d_off[i0 + 1] = run; d_cur[i0 + 1] = run; } run += v1;
        if (i0 + 2 < N_NODES) { d_off[i0 + 2] = run; d_cur[i0 + 2] = run; } run += v2;
        if (i0 + 3 < N_NODES) { d_off[i0 + 3] = run; d_cur[i0 + 3] = run; } run += v3;
        __syncthreads();
        if (tid == 0) s_carry = carry + wsum[32];
        __syncthreads();
    }
    if (tid == 0) d_off[N_NODES] = s_carry;
}

// ---------------- CSR fill (counting sort by dst) ----------------
__global__ void fill_kernel(const int* __restrict__ src, const int* __restrict__ dst) {
    int e = blockIdx.x * blockDim.x + threadIdx.x;
    if (e < N_EDGES) {
        int d = dst[e];
        int pos = atomicAdd(&d_cur[d], 1);
        d_csr_src[pos] = src[e];
    }
}

// ---------------- mean aggregation, warp per node, no float atomics ----------------
__global__ void agg_kernel(const float* __restrict__ xin, int use_h1) {
    int w = (blockIdx.x * blockDim.x + threadIdx.x) >> 5;
    int lane = threadIdx.x & 31;
    if (w >= N_NODES) return;
    const float* __restrict__ feat = use_h1 ? (const float*)d_h1 : xin;
    int beg = d_off[w], end = d_off[w + 1];
    float a0 = 0.f, a1 = 0.f;
    for (int e = beg; e < end; e++) {
        int s = d_csr_src[e];
        const float* row = feat + (long)s * F1;
        a0 += __ldg(row + lane);
        if (lane < F1 - 32) a1 += __ldg(row + 32 + lane);
    }
    float inv = 1.0f / fmaxf((float)(end - beg), 1.0f);
    d_agg[(long)w * F1 + lane] = a0 * inv;
    if (lane < F1 - 32) d_agg[(long)w * F1 + 32 + lane] = a1 * inv;
}

// ---------------- fused linear layer: out = relu?([agg|self] @ [Wl;Wr] + bl) ----------------
// block: 128 threads = 4 warps; warp mt handles 4 consecutive nodes; lane jt handles
// columns jt + 32*c. POOL fuses the per-graph max-pool into the epilogue.
template <int FOUT, int NJ, bool RELU, bool POOL>
__global__ __launch_bounds__(128) void lin_kernel(
    const float* __restrict__ xin, const float* __restrict__ Wl,
    const float* __restrict__ bl, const float* __restrict__ Wr,
    const int* __restrict__ batch)
{
    __shared__ float sW[KDIM * FOUT];
    __shared__ float sA[16 * KDIM];
    __shared__ float sbl[FOUT];

    const float* __restrict__ feat = POOL ? (const float*)d_h1 : xin;
    const int tid = threadIdx.x;
    const int jt = tid & 31;
    const int mt = tid >> 5;
    const int base_n = blockIdx.x * 16;

    // load W = [Wl; Wr] into shared
    for (int idx = tid; idx < KDIM * FOUT; idx += 128) {
        int k = idx / FOUT, j = idx - k * FOUT;
        sW[idx] = (k < F1) ? Wl[k * FOUT + j] : Wr[(k - F1) * FOUT + j];
    }
    if (tid < FOUT) sbl[tid] = bl[tid];
    // load A = [agg | self] rows for 16 nodes
    for (int idx = tid; idx < 16 * F1; idx += 128) {
        int m = idx / F1, k = idx - m * F1;
        long n = base_n + m;
        sA[m * KDIM + k]      = d_agg[n * F1 + k];
        sA[m * KDIM + F1 + k] = feat[n * F1 + k];
    }
    __syncthreads();

    float acc[4][NJ];
#pragma unroll
    for (int r = 0; r < 4; r++)
#pragma unroll
        for (int c = 0; c < NJ; c++) acc[r][c] = 0.f;

#pragma unroll 2
    for (int k = 0; k < KDIM; k++) {
        float a[4];
#pragma unroll
        for (int r = 0; r < 4; r++) a[r] = sA[(mt * 4 + r) * KDIM + k];
#pragma unroll
        for (int c = 0; c < NJ; c++) {
            int j = jt + 32 * c;
            float w = (j < FOUT) ? sW[k * FOUT + j] : 0.f;
#pragma unroll
            for (int r = 0; r < 4; r++) acc[r][c] += a[r] * w;
        }
    }

    const int n0 = base_n + mt * 4;
    if (POOL) {
        int b[4];
#pragma unroll
        for (int r = 0; r < 4; r++) b[r] = batch[n0 + r];
#pragma unroll
        for (int c = 0; c < NJ; c++) {
            int j = jt + 32 * c;
            if (j < FOUT) {
                int prevb = -1, best = 0;
#pragma unroll
                for (int r = 0; r < 4; r++) {
                    int key = fkey(acc[r][c] + sbl[j]);
                    if (b[r] != prevb) {
                        if (prevb >= 0) atomicMax(&d_gmax[prevb * F2 + j], best);
                        prevb = b[r];
                        best = key;
                    } else {
                        best = max(best, key);
                    }
                }
                atomicMax(&d_gmax[prevb * F2 + j], best);
            }
        }
    } else {
#pragma unroll
        for (int c = 0; c < NJ; c++) {
            int j = jt + 32 * c;
            if (j < FOUT) {
#pragma unroll
                for (int r = 0; r < 4; r++) {
                    float v = acc[r][c] + sbl[j];
                    if (RELU) v = fmaxf(v, 0.f);
                    d_h1[(long)(n0 + r) * FOUT + j] = v;
                }
            }
        }
    }
}

// ---------------- FC head: one block per graph ----------------
__global__ __launch_bounds__(128) void head_kernel(
    const float* __restrict__ Wg1, const float* __restrict__ bg1,
    const float* __restrict__ Wg2, const float* __restrict__ bg2,
    const float* __restrict__ Wo,  const float* __restrict__ bo,
    float* __restrict__ out)
{
    int g = blockIdx.x, j = threadIdx.x;
    __shared__ float r0[F2], r1[F2];
    __shared__ float wred[4];
    int key = d_gmax[g * F2 + j];
    key = key >= 0 ? key : (key ^ 0x7FFFFFFF);
    r0[j] = __int_as_float(key);
    __syncthreads();
    float acc = bg1[j];
#pragma unroll 8
    for (int k = 0; k < F2; k++) acc += r0[k] * Wg1[k * F2 + j];
    r1[j] = fmaxf(acc, 0.f);
    __syncthreads();
    acc = bg2[j];
#pragma unroll 8
    for (int k = 0; k < F2; k++) acc += r1[k] * Wg2[k * F2 + j];
    float v = fmaxf(acc, 0.f) * Wo[j];
#pragma unroll
    for (int s = 16; s > 0; s >>= 1) v += __shfl_down_sync(0xffffffffu, v, s);
    if ((j & 31) == 0) wred[j >> 5] = v;
    __syncthreads();
    if (j == 0) out[g] = wred[0] + wred[1] + wred[2] + wred[3] + bo[0];
}

// ---------------- launcher ----------------
extern "C" void kernel_launch(void* const* d_in, const int* in_sizes, int n_in,
                              void* d_out, int out_size) {
    const float* x    = (const float*)d_in[0];
    const int*   ei   = (const int*)d_in[1];
    const int*   bat  = (const int*)d_in[2];
    const float* Wl1  = (const float*)d_in[3];
    const float* bl1  = (const float*)d_in[4];
    const float* Wr1  = (const float*)d_in[5];
    const float* Wl2  = (const float*)d_in[6];
    const float* bl2  = (const float*)d_in[7];
    const float* Wr2  = (const float*)d_in[8];
    const float* Wg1  = (const float*)d_in[9];
    const float* bg1  = (const float*)d_in[10];
    const float* Wg2  = (const float*)d_in[11];
    const float* bg2  = (const float*)d_in[12];
    const float* Wo   = (const float*)d_in[13];
    const float* bo   = (const float*)d_in[14];
    float* out = (float*)d_out;

    const int* src = ei;
    const int* dst = ei + N_EDGES;

    init_kernel<<<(N_NODES + 255) / 256, 256>>>();
    count_kernel<<<(N_EDGES + 255) / 256, 256>>>(dst);
    scan_kernel<<<1, 1024>>>();
    fill_kernel<<<(N_EDGES + 255) / 256, 256>>>(src, dst);

    // layer 1: agg(x) -> lin1 (relu) -> d_h1
    agg_kernel<<<(N_NODES * 32 + 255) / 256, 256>>>(x, 0);
    lin_kernel<F1, 2, true, false><<<N_NODES / 16, 128>>>(x, Wl1, bl1, Wr1, bat);

    // layer 2: agg(h1) -> lin2 + fused max-pool -> d_gmax
    agg_kernel<<<(N_NODES * 32 + 255) / 256, 256>>>(x, 1);
    lin_kernel<F2, 4, false, true><<<N_NODES / 16, 128>>>(x, Wl2, bl2, Wr2, bat);

    // head
    head_kernel<<<N_GRAPHS, F2>>>(Wg1, bg1, Wg2, bg2, Wo, bo, out);
}

// round 3
// speedup vs baseline: 1.3465x; 1.3465x over previous
#include <cuda_runtime.h>
#include <cuda_fp16.h>

#define N_NODES  100000
#define N_EDGES  3200000
#define N_GRAPHS 512
#define F1 35
#define F2 128
#define KDIM 70
#define NB ((N_NODES + 1023) / 1024)   // 98 scan blocks

// ---------------- device scratch ----------------
__device__ int    d_cnt[N_NODES];
__device__ int    d_off[N_NODES + 1];
__device__ int    d_cur[N_NODES];
__device__ int    d_bsum[NB];
__device__ int    d_csr_src[N_EDGES];
__device__ float  d_agg[N_NODES * F1];
__device__ float  d_h1[N_NODES * F1];
__device__ __half d_xh[N_NODES * 64];   // padded fp16 feature rows (one 128B line per row)
__device__ int    d_gmax[N_GRAPHS * F2];

// packed f32x2 FMA (Blackwell): d = a*b + c elementwise on 2 packed floats
#define FMA_F32X2(d, a, b, c) \
    asm("fma.rn.f32x2 %0, %1, %2, %3;" : "=l"(d) : "l"(a), "l"(b), "l"(c))
#define PACK_F32X2(out, lo, hi) \
    asm("mov.b64 %0, {%1, %2};" : "=l"(out) : "f"(lo), "f"(hi))
#define UNPACK_F32X2(lo, hi, in) \
    asm("mov.b64 {%0, %1}, %2;" : "=f"(lo), "=f"(hi) : "l"(in))

__device__ __forceinline__ int fkey(float f) {
    int i = __float_as_int(f);
    return i >= 0 ? i : (i ^ 0x7FFFFFFF);
}

// ---------------- init ----------------
__global__ void init_kernel() {
    int i = blockIdx.x * blockDim.x + threadIdx.x;
    if (i < N_NODES) d_cnt[i] = 0;
    if (i < N_GRAPHS * F2) d_gmax[i] = (int)0x807FFFFFu;  // fkey(-inf)
}

// ---------------- degree count ----------------
__global__ void count_kernel(const int* __restrict__ dst) {
    int e = blockIdx.x * blockDim.x + threadIdx.x;
    if (e < N_EDGES) atomicAdd(&d_cnt[dst[e]], 1);
}

// ---------------- parallel scan (3 kernels) ----------------
__global__ __launch_bounds__(1024) void scan_part_kernel() {
    __shared__ int ws[32];
    int b = blockIdx.x, t = threadIdx.x;
    int i = b * 1024 + t;
    int v = (i < N_NODES) ? d_cnt[i] : 0;
    int s = v;
#pragma unroll
    for (int o = 16; o > 0; o >>= 1) s += __shfl_down_sync(0xffffffffu, s, o);
    if ((t & 31) == 0) ws[t >> 5] = s;
    __syncthreads();
    if (t < 32) {
        int x = ws[t];
#pragma unroll
        for (int o = 16; o > 0; o >>= 1) x += __shfl_down_sync(0xffffffffu, x, o);
        if (t == 0) d_bsum[b] = x;
    }
}

__global__ void scan_top_kernel() {
    __shared__ int s[NB];
    int t = threadIdx.x;
    if (t < NB) s[t] = d_bsum[t];
    __syncthreads();
    if (t == 0) {
        int run = 0;
        for (int b = 0; b < NB; b++) { int v = s[b]; s[b] = run; run += v; }
    }
    __syncthreads();
    if (t < NB) d_bsum[t] = s[t];
}

__global__ __launch_bounds__(1024) void scan_scatter_kernel() {
    __shared__ int ws[32];
    int b = blockIdx.x, t = threadIdx.x;
    int lane = t & 31, wid = t >> 5;
    int i = b * 1024 + t;
    int v = (i < N_NODES) ? d_cnt[i] : 0;
    int incl = v;
#pragma unroll
    for (int o = 1; o < 32; o <<= 1) {
        int x = __shfl_up_sync(0xffffffffu, incl, o);
        if (lane >= o) incl += x;
    }
    if (lane == 31) ws[wid] = incl;
    __syncthreads();
    if (t < 32) {
        int x = ws[t], xi = x;
#pragma unroll
        for (int o = 1; o < 32; o <<= 1) {
            int y = __shfl_up_sync(0xffffffffu, xi, o);
            if (lane >= o) xi += y;
        }
        ws[t] = xi - x;
    }
    __syncthreads();
    int ex = d_bsum[b] + ws[wid] + (incl - v);
    if (i < N_NODES) {
        d_off[i] = ex;
        d_cur[i] = ex;
        if (i == N_NODES - 1) d_off[N_NODES] = ex + v;
    }
}

// ---------------- CSR fill ----------------
__global__ void fill_kernel(const int* __restrict__ src, const int* __restrict__ dst) {
    int e = blockIdx.x * blockDim.x + threadIdx.x;
    if (e < N_EDGES) {
        int d = dst[e];
        int pos = atomicAdd(&d_cur[d], 1);
        d_csr_src[pos] = src[e];
    }
}

// ---------------- fp32 [N,35] -> fp16 padded [N,64] ----------------
// use_h1 selects d_h1 (device symbol resolved in DEVICE code) vs. input x.
__global__ void conv_kernel(const float* __restrict__ xin, int use_h1) {
    int i = blockIdx.x * blockDim.x + threadIdx.x;   // over N_NODES*32 half2 slots
    if (i >= N_NODES * 32) return;
    const float* __restrict__ in = use_h1 ? (const float*)d_h1 : xin;
    int n = i >> 5, c = i & 31;
    int f0 = 2 * c, f1 = 2 * c + 1;
    float v0 = (f0 < F1) ? in[n * F1 + f0] : 0.f;
    float v1 = (f1 < F1) ? in[n * F1 + f1] : 0.f;
    ((__half2*)d_xh)[i] = __floats2half2_rn(v0, v1);
}

// ---------------- mean aggregation: warp per node, 4 edges/iter via LDG.128 ----------------
__global__ __launch_bounds__(256) void agg_kernel() {
    int w = (blockIdx.x * blockDim.x + threadIdx.x) >> 5;   // node
    int lane = threadIdx.x & 31;
    if (w >= N_NODES) return;
    int g = lane >> 3;        // edge group 0..3
    int p = lane & 7;         // 16B slice within row -> features 8p..8p+7
    int beg = d_off[w], end = d_off[w + 1];

    float acc[8];
#pragma unroll
    for (int i = 0; i < 8; i++) acc[i] = 0.f;

    const uint4* __restrict__ xh4 = (const uint4*)d_xh;
#pragma unroll 2
    for (int e0 = beg; e0 < end; e0 += 4) {
        int e = e0 + g;
        if (e < end) {
            int s = d_csr_src[e];
            uint4 v = __ldg(&xh4[(long)s * 8 + p]);
            float2 f;
            f = __half22float2(*(__half2*)&v.x); acc[0] += f.x; acc[1] += f.y;
            f = __half22float2(*(__half2*)&v.y); acc[2] += f.x; acc[3] += f.y;
            f = __half22float2(*(__half2*)&v.z); acc[4] += f.x; acc[5] += f.y;
            f = __half22float2(*(__half2*)&v.w); acc[6] += f.x; acc[7] += f.y;
        }
    }
    // reduce the 4 edge groups (lanes p, p+8, p+16, p+24)
#pragma unroll
    for (int i = 0; i < 8; i++) {
        acc[i] += __shfl_xor_sync(0xffffffffu, acc[i], 8);
        acc[i] += __shfl_xor_sync(0xffffffffu, acc[i], 16);
    }
    float inv = 1.0f / fmaxf((float)(end - beg), 1.0f);
    if (lane < 8) {
#pragma unroll
        for (int i = 0; i < 8; i++) {
            int f = lane * 8 + i;
            if (f < F1) d_agg[(long)w * F1 + f] = acc[i] * inv;
        }
    }
}

// ---------------- fused linear: out = relu?([agg|self] @ [Wl;Wr] + bl), FFMA2 ----------------
// 256 threads, 32 nodes/block. warp mt handles nodes mt*4..mt*4+3; lane jt covers
// cols jt+32c. sAT is transposed [k][36] so a-rows load as one broadcast LDS.128.
template <int FOUT, int NJ, bool RELU, bool POOL>
__global__ __launch_bounds__(256) void lin_kernel(
    const float* __restrict__ xin, const float* __restrict__ Wl,
    const float* __restrict__ bl, const float* __restrict__ Wr,
    const int* __restrict__ batch)
{
    __shared__ __align__(16) float sAT[KDIM][36];
    __shared__ float sW[KDIM * FOUT];
    __shared__ float sbl[FOUT];

    const float* __restrict__ feat = POOL ? (const float*)d_h1 : xin;
    const int tid = threadIdx.x;
    const int jt = tid & 31;
    const int mt = tid >> 5;              // 0..7
    const int base_n = blockIdx.x * 32;

    for (int idx = tid; idx < KDIM * FOUT; idx += 256) {
        int k = idx / FOUT, j = idx - k * FOUT;
        sW[idx] = (k < F1) ? Wl[k * FOUT + j] : Wr[(k - F1) * FOUT + j];
    }
    if (tid < FOUT) sbl[tid] = bl[tid];
    for (int idx = tid; idx < 32 * F1; idx += 256) {
        int m = idx & 31, k = idx >> 5;
        long n = base_n + m;
        sAT[k][m]      = d_agg[n * F1 + k];
        sAT[k + F1][m] = feat[n * F1 + k];
    }
    __syncthreads();

    unsigned long long acc2[2][NJ];
#pragma unroll
    for (int p = 0; p < 2; p++)
#pragma unroll
        for (int c = 0; c < NJ; c++) acc2[p][c] = 0ULL;

#pragma unroll 2
    for (int k = 0; k < KDIM; k++) {
        float4 a4 = *(const float4*)&sAT[k][mt * 4];
        unsigned long long a01, a23;
        PACK_F32X2(a01, a4.x, a4.y);
        PACK_F32X2(a23, a4.z, a4.w);
#pragma unroll
        for (int c = 0; c < NJ; c++) {
            int j = jt + 32 * c;
            float w = (j < FOUT) ? sW[k * FOUT + j] : 0.f;
            unsigned long long ww;
            PACK_F32X2(ww, w, w);
            FMA_F32X2(acc2[0][c], a01, ww, acc2[0][c]);
            FMA_F32X2(acc2[1][c], a23, ww, acc2[1][c]);
        }
    }

    const int n0 = base_n + mt * 4;
    float v[4];
    if (POOL) {
        int b[4];
#pragma unroll
        for (int r = 0; r < 4; r++) b[r] = batch[n0 + r];
#pragma unroll
        for (int c = 0; c < NJ; c++) {
            int j = jt + 32 * c;
            if (j < FOUT) {
                UNPACK_F32X2(v[0], v[1], acc2[0][c]);
                UNPACK_F32X2(v[2], v[3], acc2[1][c]);
                int prevb = -1, best = 0;
#pragma unroll
                for (int r = 0; r < 4; r++) {
                    int key = fkey(v[r] + sbl[j]);
                    if (b[r] != prevb) {
                        if (prevb >= 0) atomicMax(&d_gmax[prevb * F2 + j], best);
                        prevb = b[r];
                        best = key;
                    } else {
                        best = max(best, key);
                    }
                }
                atomicMax(&d_gmax[prevb * F2 + j], best);
            }
        }
    } else {
#pragma unroll
        for (int c = 0; c < NJ; c++) {
            int j = jt + 32 * c;
            if (j < FOUT) {
                UNPACK_F32X2(v[0], v[1], acc2[0][c]);
                UNPACK_F32X2(v[2], v[3], acc2[1][c]);
#pragma unroll
                for (int r = 0; r < 4; r++) {
                    float o = v[r] + sbl[j];
                    if (RELU) o = fmaxf(o, 0.f);
                    d_h1[(long)(n0 + r) * FOUT + j] = o;
                }
            }
        }
    }
}

// ---------------- FC head ----------------
__global__ __launch_bounds__(128) void head_kernel(
    const float* __restrict__ Wg1, const float* __restrict__ bg1,
    const float* __restrict__ Wg2, const float* __restrict__ bg2,
    const float* __restrict__ Wo,  const float* __restrict__ bo,
    float* __restrict__ out)
{
    int g = blockIdx.x, j = threadIdx.x;
    __shared__ float r0[F2], r1[F2];
    __shared__ float wred[4];
    int key = d_gmax[g * F2 + j];
    key = key >= 0 ? key : (key ^ 0x7FFFFFFF);
    r0[j] = __int_as_float(key);
    __syncthreads();
    float acc = bg1[j];
#pragma unroll 8
    for (int k = 0; k < F2; k++) acc += r0[k] * Wg1[k * F2 + j];
    r1[j] = fmaxf(acc, 0.f);
    __syncthreads();
    acc = bg2[j];
#pragma unroll 8
    for (int k = 0; k < F2; k++) acc += r1[k] * Wg2[k * F2 + j];
    float v = fmaxf(acc, 0.f) * Wo[j];
#pragma unroll
    for (int s = 16; s > 0; s >>= 1) v += __shfl_down_sync(0xffffffffu, v, s);
    if ((j & 31) == 0) wred[j >> 5] = v;
    __syncthreads();
    if (j == 0) out[g] = wred[0] + wred[1] + wred[2] + wred[3] + bo[0];
}

// ---------------- launcher ----------------
extern "C" void kernel_launch(void* const* d_in, const int* in_sizes, int n_in,
                              void* d_out, int out_size) {
    const float* x    = (const float*)d_in[0];
    const int*   ei   = (const int*)d_in[1];
    const int*   bat  = (const int*)d_in[2];
    const float* Wl1  = (const float*)d_in[3];
    const float* bl1  = (const float*)d_in[4];
    const float* Wr1  = (const float*)d_in[5];
    const float* Wl2  = (const float*)d_in[6];
    const float* bl2  = (const float*)d_in[7];
    const float* Wr2  = (const float*)d_in[8];
    const float* Wg1  = (const float*)d_in[9];
    const float* bg1  = (const float*)d_in[10];
    const float* Wg2  = (const float*)d_in[11];
    const float* bg2  = (const float*)d_in[12];
    const float* Wo   = (const float*)d_in[13];
    const float* bo   = (const float*)d_in[14];
    float* out = (float*)d_out;

    const int* src = ei;
    const int* dst = ei + N_EDGES;

    init_kernel<<<(N_NODES + 255) / 256, 256>>>();
    count_kernel<<<(N_EDGES + 255) / 256, 256>>>(dst);
    scan_part_kernel<<<NB, 1024>>>();
    scan_top_kernel<<<1, 128>>>();
    scan_scatter_kernel<<<NB, 1024>>>();
    fill_kernel<<<(N_EDGES + 255) / 256, 256>>>(src, dst);

    // layer 1
    conv_kernel<<<(N_NODES * 32 + 255) / 256, 256>>>(x, 0);
    agg_kernel<<<(N_NODES * 32 + 255) / 256, 256>>>();
    lin_kernel<F1, 2, true, false><<<N_NODES / 32, 256>>>(x, Wl1, bl1, Wr1, bat);

    // layer 2 (+ fused max pool)
    conv_kernel<<<(N_NODES * 32 + 255) / 256, 256>>>(x, 1);
    agg_kernel<<<(N_NODES * 32 + 255) / 256, 256>>>();
    lin_kernel<F2, 4, false, true><<<N_NODES / 32, 256>>>(x, Wl2, bl2, Wr2, bat);

    head_kernel<<<N_GRAPHS, F2>>>(Wg1, bg1, Wg2, bg2, Wo, bo, out);
}

// round 4
// speedup vs baseline: 1.4818x; 1.1005x over previous
#include <cuda_runtime.h>
#include <cuda_fp16.h>

#define N_NODES  100000
#define N_EDGES  3200000
#define N_GRAPHS 512
#define F1 35
#define F2 128
#define KDIM 70
#define RPAD 48                         // fp16 row padded to 48 halves = 96B = 3 sectors
#define NB ((N_NODES + 1023) / 1024)    // 98 scan blocks
#define CNT_BLK ((N_EDGES + 255) / 256) // 12500
#define CONV_BLK (N_NODES * 24 / 256)   // 9375 (N_NODES*24 half2 slots)

// ---------------- device scratch (zero-initialized at load) ----------------
__device__ int    d_cnt[N_NODES];        // re-zeroed by scan_scatter each call
__device__ int    d_off[N_NODES + 1];
__device__ int    d_cur[N_NODES];
__device__ int    d_bsum[NB];
__device__ int    d_csr_src[N_EDGES];
__device__ float  d_agg[N_NODES * F1];
__device__ __half d_xh[N_NODES * RPAD];  // padded fp16 rows; pads stay 0 forever
__device__ int    d_gmax[N_GRAPHS * F2];

#define FMA_F32X2(d, a, b, c) \
    asm("fma.rn.f32x2 %0, %1, %2, %3;" : "=l"(d) : "l"(a), "l"(b), "l"(c))
#define PACK_F32X2(out, lo, hi) \
    asm("mov.b64 %0, {%1, %2};" : "=l"(out) : "f"(lo), "f"(hi))
#define UNPACK_F32X2(lo, hi, in) \
    asm("mov.b64 {%0, %1}, %2;" : "=f"(lo), "=f"(hi) : "l"(in))

__device__ __forceinline__ int fkey(float f) {
    int i = __float_as_int(f);
    return i >= 0 ? i : (i ^ 0x7FFFFFFF);
}

// ---------------- K1: degree count + conv(x -> fp16 padded rows), fused ----------------
__global__ void pre_kernel(const float* __restrict__ x, const int* __restrict__ dst) {
    int b = blockIdx.x, t = threadIdx.x;
    if (b < CNT_BLK) {
        int e = b * 256 + t;
        if (e < N_EDGES) atomicAdd(&d_cnt[dst[e]], 1);
    } else {
        int i = (b - CNT_BLK) * 256 + t;          // half2 slot
        if (i < N_NODES * 24) {
            int n = i / 24, c = i - n * 24;
            int f0 = 2 * c, f1 = 2 * c + 1;
            float v0 = (f0 < F1) ? x[n * F1 + f0] : 0.f;
            float v1 = (f1 < F1) ? x[n * F1 + f1] : 0.f;
            ((__half2*)d_xh)[n * 24 + c] = __floats2half2_rn(v0, v1);
        }
    }
}

// ---------------- scan part sums (+ d_gmax reset) ----------------
__global__ __launch_bounds__(1024) void scan_part_kernel() {
    __shared__ int ws[32];
    int b = blockIdx.x, t = threadIdx.x;
    int i = b * 1024 + t;
    if (i < N_GRAPHS * F2) d_gmax[i] = (int)0x807FFFFFu;   // fkey(-inf)
    int v = (i < N_NODES) ? d_cnt[i] : 0;
    int s = v;
#pragma unroll
    for (int o = 16; o > 0; o >>= 1) s += __shfl_down_sync(0xffffffffu, s, o);
    if ((t & 31) == 0) ws[t >> 5] = s;
    __syncthreads();
    if (t < 32) {
        int x = ws[t];
#pragma unroll
        for (int o = 16; o > 0; o >>= 1) x += __shfl_down_sync(0xffffffffu, x, o);
        if (t == 0) d_bsum[b] = x;
    }
}

// ---------------- scan scatter (inline top prefix; re-zeroes d_cnt) ----------------
__global__ __launch_bounds__(1024) void scan_scatter_kernel() {
    __shared__ int ws[32];
    __shared__ int sc[4];
    int b = blockIdx.x, t = threadIdx.x;
    int lane = t & 31, wid = t >> 5;

    // inline prefix over block sums: carry = sum_{j<b} d_bsum[j]
    if (t < 128) {
        int pv = (t < NB && t < b) ? d_bsum[t] : 0;
#pragma unroll
        for (int o = 16; o > 0; o >>= 1) pv += __shfl_down_sync(0xffffffffu, pv, o);
        if (lane == 0) sc[wid] = pv;
    }

    int i = b * 1024 + t;
    int v = (i < N_NODES) ? d_cnt[i] : 0;
    int incl = v;
#pragma unroll
    for (int o = 1; o < 32; o <<= 1) {
        int x = __shfl_up_sync(0xffffffffu, incl, o);
        if (lane >= o) incl += x;
    }
    if (lane == 31) ws[wid] = incl;
    __syncthreads();
    int carry = sc[0] + sc[1] + sc[2] + sc[3];
    if (t < 32) {
        int x = ws[t], xi = x;
#pragma unroll
        for (int o = 1; o < 32; o <<= 1) {
            int y = __shfl_up_sync(0xffffffffu, xi, o);
            if (lane >= o) xi += y;
        }
        ws[t] = xi - x;
    }
    __syncthreads();
    int ex = carry + ws[wid] + (incl - v);
    if (i < N_NODES) {
        d_off[i] = ex;
        d_cur[i] = ex;
        d_cnt[i] = 0;                      // reset for next call (graph replay invariant)
        if (i == N_NODES - 1) d_off[N_NODES] = ex + v;
    }
}

// ---------------- CSR fill ----------------
__global__ void fill_kernel(const int* __restrict__ src, const int* __restrict__ dst) {
    int e = blockIdx.x * blockDim.x + threadIdx.x;
    if (e < N_EDGES) {
        int d = dst[e];
        int pos = atomicAdd(&d_cur[d], 1);
        d_csr_src[pos] = src[e];
    }
}

// ---------------- mean aggregation: warp/node, 5 edges/iter, 96B (3 sectors) per row ----------------
__global__ __launch_bounds__(256) void agg_kernel() {
    int w = (blockIdx.x * blockDim.x + threadIdx.x) >> 5;   // node
    int lane = threadIdx.x & 31;
    if (w >= N_NODES) return;
    int g = lane / 6;            // edge group 0..4 (lanes 30,31 -> g=5, inactive)
    int p = lane - g * 6;        // 16B slice -> features 8p..8p+7
    bool active = g < 5;
    int beg = d_off[w], end = d_off[w + 1];

    float acc[8];
#pragma unroll
    for (int i = 0; i < 8; i++) acc[i] = 0.f;

    const uint4* __restrict__ xh4 = (const uint4*)d_xh;     // row = 6 uint4
#pragma unroll 2
    for (int e0 = beg; e0 < end; e0 += 5) {
        int e = e0 + g;
        if (active && e < end) {
            int s = d_csr_src[e];
            uint4 v = __ldg(&xh4[(long)s * 6 + p]);
            float2 f;
            f = __half22float2(*(__half2*)&v.x); acc[0] += f.x; acc[1] += f.y;
            f = __half22float2(*(__half2*)&v.y); acc[2] += f.x; acc[3] += f.y;
            f = __half22float2(*(__half2*)&v.z); acc[4] += f.x; acc[5] += f.y;
            f = __half22float2(*(__half2*)&v.w); acc[6] += f.x; acc[7] += f.y;
        }
    }
    // gather-sum the 5 groups (lanes p, p+6, p+12, p+18, p+24)
#pragma unroll
    for (int i = 0; i < 8; i++) {
        float t1 = __shfl_sync(0xffffffffu, acc[i], lane + 6);
        float t2 = __shfl_sync(0xffffffffu, acc[i], lane + 12);
        float t3 = __shfl_sync(0xffffffffu, acc[i], lane + 18);
        float t4 = __shfl_sync(0xffffffffu, acc[i], lane + 24);
        acc[i] += t1 + t2 + t3 + t4;
    }
    float inv = 1.0f / fmaxf((float)(end - beg), 1.0f);
    if (lane < 6) {
#pragma unroll
        for (int i = 0; i < 8; i++) {
            int f = lane * 8 + i;
            if (f < F1) d_agg[(long)w * F1 + f] = acc[i] * inv;
        }
    }
}

// ---------------- fused linear (FFMA2). lin1 writes fp16 h1 rows; lin2 fuses max-pool ----------------
template <int FOUT, int NJ, bool POOL>
__global__ __launch_bounds__(256) void lin_kernel(
    const float* __restrict__ xin, const float* __restrict__ Wl,
    const float* __restrict__ bl, const float* __restrict__ Wr,
    const int* __restrict__ batch)
{
    __shared__ __align__(16) float sAT[KDIM][36];
    __shared__ float sW[KDIM * FOUT];
    __shared__ float sbl[FOUT];

    const int tid = threadIdx.x;
    const int jt = tid & 31;
    const int mt = tid >> 5;              // 0..7
    const int base_n = blockIdx.x * 32;

    for (int idx = tid; idx < KDIM * FOUT; idx += 256) {
        int k = idx / FOUT, j = idx - k * FOUT;
        sW[idx] = (k < F1) ? Wl[k * FOUT + j] : Wr[(k - F1) * FOUT + j];
    }
    if (tid < FOUT) sbl[tid] = bl[tid];
    for (int idx = tid; idx < 32 * F1; idx += 256) {
        int m = idx & 31, k = idx >> 5;
        long n = base_n + m;
        sAT[k][m] = d_agg[n * F1 + k];
        if (POOL) sAT[k + F1][m] = __half2float(d_xh[n * RPAD + k]);  // self = fp16 h1
        else      sAT[k + F1][m] = xin[n * F1 + k];                   // self = fp32 x
    }
    __syncthreads();

    unsigned long long acc2[2][NJ];
#pragma unroll
    for (int p = 0; p < 2; p++)
#pragma unroll
        for (int c = 0; c < NJ; c++) acc2[p][c] = 0ULL;

#pragma unroll 2
    for (int k = 0; k < KDIM; k++) {
        float4 a4 = *(const float4*)&sAT[k][mt * 4];
        unsigned long long a01, a23;
        PACK_F32X2(a01, a4.x, a4.y);
        PACK_F32X2(a23, a4.z, a4.w);
#pragma unroll
        for (int c = 0; c < NJ; c++) {
            int j = jt + 32 * c;
            float w = (j < FOUT) ? sW[k * FOUT + j] : 0.f;
            unsigned long long ww;
            PACK_F32X2(ww, w, w);
            FMA_F32X2(acc2[0][c], a01, ww, acc2[0][c]);
            FMA_F32X2(acc2[1][c], a23, ww, acc2[1][c]);
        }
    }

    const int n0 = base_n + mt * 4;
    float v[4];
    if (POOL) {
        int b[4];
#pragma unroll
        for (int r = 0; r < 4; r++) b[r] = batch[n0 + r];
#pragma unroll
        for (int c = 0; c < NJ; c++) {
            int j = jt + 32 * c;
            if (j < FOUT) {
                UNPACK_F32X2(v[0], v[1], acc2[0][c]);
                UNPACK_F32X2(v[2], v[3], acc2[1][c]);
                int prevb = -1, best = 0;
#pragma unroll
                for (int r = 0; r < 4; r++) {
                    int key = fkey(v[r] + sbl[j]);
                    if (b[r] != prevb) {
                        if (prevb >= 0) atomicMax(&d_gmax[prevb * F2 + j], best);
                        prevb = b[r];
                        best = key;
                    } else {
                        best = max(best, key);
                    }
                }
                atomicMax(&d_gmax[prevb * F2 + j], best);
            }
        }
    } else {
        // lin1: relu, store as padded fp16 rows (pads untouched -> stay 0)
#pragma unroll
        for (int c = 0; c < NJ; c++) {
            int j = jt + 32 * c;
            if (j < FOUT) {
                UNPACK_F32X2(v[0], v[1], acc2[0][c]);
                UNPACK_F32X2(v[2], v[3], acc2[1][c]);
#pragma unroll
                for (int r = 0; r < 4; r++) {
                    float o = fmaxf(v[r] + sbl[j], 0.f);
                    d_xh[(long)(n0 + r) * RPAD + j] = __float2half(o);
                }
            }
        }
    }
}

// ---------------- FC head ----------------
__global__ __launch_bounds__(128) void head_kernel(
    const float* __restrict__ Wg1, const float* __restrict__ bg1,
    const float* __restrict__ Wg2, const float* __restrict__ bg2,
    const float* __restrict__ Wo,  const float* __restrict__ bo,
    float* __restrict__ out)
{
    int g = blockIdx.x, j = threadIdx.x;
    __shared__ float r0[F2], r1[F2];
    __shared__ float wred[4];
    int key = d_gmax[g * F2 + j];
    key = key >= 0 ? key : (key ^ 0x7FFFFFFF);
    r0[j] = __int_as_float(key);
    __syncthreads();
    float acc = bg1[j];
#pragma unroll 8
    for (int k = 0; k < F2; k++) acc += r0[k] * Wg1[k * F2 + j];
    r1[j] = fmaxf(acc, 0.f);
    __syncthreads();
    acc = bg2[j];
#pragma unroll 8
    for (int k = 0; k < F2; k++) acc += r1[k] * Wg2[k * F2 + j];
    float v = fmaxf(acc, 0.f) * Wo[j];
#pragma unroll
    for (int s = 16; s > 0; s >>= 1) v += __shfl_down_sync(0xffffffffu, v, s);
    if ((j & 31) == 0) wred[j >> 5] = v;
    __syncthreads();
    if (j == 0) out[g] = wred[0] + wred[1] + wred[2] + wred[3] + bo[0];
}

// ---------------- launcher (9 kernels) ----------------
extern "C" void kernel_launch(void* const* d_in, const int* in_sizes, int n_in,
                              void* d_out, int out_size) {
    const float* x    = (const float*)d_in[0];
    const int*   ei   = (const int*)d_in[1];
    const int*   bat  = (const int*)d_in[2];
    const float* Wl1  = (const float*)d_in[3];
    const float* bl1  = (const float*)d_in[4];
    const float* Wr1  = (const float*)d_in[5];
    const float* Wl2  = (const float*)d_in[6];
    const float* bl2  = (const float*)d_in[7];
    const float* Wr2  = (const float*)d_in[8];
    const float* Wg1  = (const float*)d_in[9];
    const float* bg1  = (const float*)d_in[10];
    const float* Wg2  = (const float*)d_in[11];
    const float* bg2  = (const float*)d_in[12];
    const float* Wo   = (const float*)d_in[13];
    const float* bo   = (const float*)d_in[14];
    float* out = (float*)d_out;

    const int* src = ei;
    const int* dst = ei + N_EDGES;

    pre_kernel<<<CNT_BLK + CONV_BLK, 256>>>(x, dst);   // count + conv1 (+ gmax via scan_part)
    scan_part_kernel<<<NB, 1024>>>();
    scan_scatter_kernel<<<NB, 1024>>>();
    fill_kernel<<<CNT_BLK, 256>>>(src, dst);

    agg_kernel<<<(N_NODES * 32 + 255) / 256, 256>>>();                       // agg(x)
    lin_kernel<F1, 2, false><<<N_NODES / 32, 256>>>(x, Wl1, bl1, Wr1, bat);  // -> fp16 h1

    agg_kernel<<<(N_NODES * 32 + 255) / 256, 256>>>();                       // agg(h1)
    lin_kernel<F2, 4, true><<<N_NODES / 32, 256>>>(x, Wl2, bl2, Wr2, bat);   // + max pool

    head_kernel<<<N_GRAPHS, F2>>>(Wg1, bg1, Wg2, bg2, Wo, bo, out);
}